// round 1
// baseline (speedup 1.0000x reference)
#include <cuda_runtime.h>
#include <math.h>

#define DIM 1024
#define NQ 4096
#define NKV 4096
#define NH 16
#define HD 64
#define SCALE 0.125f   // 64^-0.5

// ---------------- scratch (device globals; no allocation allowed) ----------
__device__ float g_Q[NQ * DIM];
__device__ float g_K[NKV * DIM];
__device__ float g_V[NKV * DIM];
__device__ float g_AO[NQ * DIM];

// ---------------- GEMM: C[M,N] = X[M,K] @ W[N,K]^T + b -------------------
// BM=BN=128, BK=16, 256 threads, 8x8 microtile per thread.
#define GBM 128
#define GBN 128
#define GBK 16

__global__ __launch_bounds__(256)
void gemm_nt_kernel(const float* __restrict__ X, const float* __restrict__ W,
                    const float* __restrict__ bias, float* __restrict__ C,
                    int M, int N, int K) {
    __shared__ float As[GBK][GBM + 4];
    __shared__ float Bs[GBK][GBN + 4];

    const int tid = threadIdx.x;
    const int tx = tid & 15;        // 0..15 -> N microtile
    const int ty = tid >> 4;        // 0..15 -> M microtile
    const int rowBase = blockIdx.x * GBM;
    const int colBase = blockIdx.y * GBN;

    float acc[8][8];
    #pragma unroll
    for (int i = 0; i < 8; i++)
        #pragma unroll
        for (int j = 0; j < 8; j++) acc[i][j] = 0.f;

    for (int k0 = 0; k0 < K; k0 += GBK) {
        // load 128x16 of X and W (as float4), store transposed into smem
        #pragma unroll
        for (int l = 0; l < 2; l++) {
            int lin = tid + l * 256;          // 0..511
            int r   = lin >> 2;               // 0..127
            int c4  = (lin & 3) * 4;          // 0,4,8,12
            float4 a = *reinterpret_cast<const float4*>(&X[(size_t)(rowBase + r) * K + k0 + c4]);
            As[c4 + 0][r] = a.x; As[c4 + 1][r] = a.y;
            As[c4 + 2][r] = a.z; As[c4 + 3][r] = a.w;
            float4 w = *reinterpret_cast<const float4*>(&W[(size_t)(colBase + r) * K + k0 + c4]);
            Bs[c4 + 0][r] = w.x; Bs[c4 + 1][r] = w.y;
            Bs[c4 + 2][r] = w.z; Bs[c4 + 3][r] = w.w;
        }
        __syncthreads();

        #pragma unroll
        for (int kk = 0; kk < GBK; kk++) {
            float a[8], b[8];
            #pragma unroll
            for (int i = 0; i < 8; i++) a[i] = As[kk][ty * 8 + i];
            #pragma unroll
            for (int j = 0; j < 8; j++) b[j] = Bs[kk][tx * 8 + j];
            #pragma unroll
            for (int i = 0; i < 8; i++)
                #pragma unroll
                for (int j = 0; j < 8; j++)
                    acc[i][j] = fmaf(a[i], b[j], acc[i][j]);
        }
        __syncthreads();
    }

    #pragma unroll
    for (int i = 0; i < 8; i++) {
        int row = rowBase + ty * 8 + i;
        #pragma unroll
        for (int j = 0; j < 8; j++) {
            int col = colBase + tx * 8 + j;
            C[(size_t)row * N + col] = acc[i][j] + bias[col];
        }
    }
}

// ---------------- Flash attention (fp32) ----------------------------------
// grid: (NQ/64, NH). block: 256 threads. Tiles: 64 q-rows x 64 kv-rows, HD=64.
// Thread (ty,tx) owns a 4x4 microtile of the 64x64 score/output tiles.
#define AT  64
#define APAD 65

__global__ __launch_bounds__(256)
void attn_kernel(const float* __restrict__ Q, const float* __restrict__ K,
                 const float* __restrict__ V, float* __restrict__ AO) {
    extern __shared__ float smem[];
    float* Qs = smem;                    // 64 x 65
    float* Ks = Qs + AT * APAD;          // 64 x 65
    float* Vs = Ks + AT * APAD;          // 64 x 65
    float* Ps = Vs + AT * APAD;          // 64 x 65

    const int tid = threadIdx.x;
    const int tx = tid & 15;
    const int ty = tid >> 4;
    const int h = blockIdx.y;
    const int q0 = blockIdx.x * AT;
    const int colBase = h * HD;

    // load Q tile (64x64)
    #pragma unroll
    for (int l = 0; l < 4; l++) {
        int lin = tid + l * 256;         // 0..1023
        int r = lin >> 4;                // 0..63
        int c4 = (lin & 15) * 4;         // 0..60
        float4 v = *reinterpret_cast<const float4*>(&Q[(size_t)(q0 + r) * DIM + colBase + c4]);
        Qs[r * APAD + c4 + 0] = v.x; Qs[r * APAD + c4 + 1] = v.y;
        Qs[r * APAD + c4 + 2] = v.z; Qs[r * APAD + c4 + 3] = v.w;
    }
    __syncthreads();

    float o[4][4];
    float m[4], lsum[4];
    #pragma unroll
    for (int r = 0; r < 4; r++) {
        m[r] = -INFINITY; lsum[r] = 0.f;
        #pragma unroll
        for (int c = 0; c < 4; c++) o[r][c] = 0.f;
    }

    for (int kt = 0; kt < NKV / AT; kt++) {
        int kv0 = kt * AT;
        // load K,V tiles
        #pragma unroll
        for (int l = 0; l < 4; l++) {
            int lin = tid + l * 256;
            int r = lin >> 4;
            int c4 = (lin & 15) * 4;
            float4 kvec = *reinterpret_cast<const float4*>(&K[(size_t)(kv0 + r) * DIM + colBase + c4]);
            Ks[r * APAD + c4 + 0] = kvec.x; Ks[r * APAD + c4 + 1] = kvec.y;
            Ks[r * APAD + c4 + 2] = kvec.z; Ks[r * APAD + c4 + 3] = kvec.w;
            float4 vvec = *reinterpret_cast<const float4*>(&V[(size_t)(kv0 + r) * DIM + colBase + c4]);
            Vs[r * APAD + c4 + 0] = vvec.x; Vs[r * APAD + c4 + 1] = vvec.y;
            Vs[r * APAD + c4 + 2] = vvec.z; Vs[r * APAD + c4 + 3] = vvec.w;
        }
        __syncthreads();

        // S = Q @ K^T (4x4 per thread)
        float s[4][4];
        #pragma unroll
        for (int r = 0; r < 4; r++)
            #pragma unroll
            for (int c = 0; c < 4; c++) s[r][c] = 0.f;
        #pragma unroll 8
        for (int cc = 0; cc < HD; cc++) {
            float qa[4], kb[4];
            #pragma unroll
            for (int r = 0; r < 4; r++) qa[r] = Qs[(ty * 4 + r) * APAD + cc];
            #pragma unroll
            for (int c = 0; c < 4; c++) kb[c] = Ks[(tx * 4 + c) * APAD + cc];
            #pragma unroll
            for (int r = 0; r < 4; r++)
                #pragma unroll
                for (int c = 0; c < 4; c++)
                    s[r][c] = fmaf(qa[r], kb[c], s[r][c]);
        }

        // online softmax; row stats reduced across tx (lane bits 0..3)
        #pragma unroll
        for (int r = 0; r < 4; r++) {
            float tm = s[r][0];
            #pragma unroll
            for (int c = 1; c < 4; c++) tm = fmaxf(tm, s[r][c]);
            tm *= SCALE;
            #pragma unroll
            for (int msk = 1; msk < 16; msk <<= 1)
                tm = fmaxf(tm, __shfl_xor_sync(0xffffffffu, tm, msk));
            float mnew = fmaxf(m[r], tm);
            float alpha = __expf(m[r] - mnew);
            m[r] = mnew;
            float rs = 0.f;
            #pragma unroll
            for (int c = 0; c < 4; c++) {
                float p = __expf(s[r][c] * SCALE - mnew);
                s[r][c] = p;
                rs += p;
            }
            #pragma unroll
            for (int msk = 1; msk < 16; msk <<= 1)
                rs += __shfl_xor_sync(0xffffffffu, rs, msk);
            lsum[r] = lsum[r] * alpha + rs;
            #pragma unroll
            for (int c = 0; c < 4; c++) o[r][c] *= alpha;
        }

        // stage P to smem
        #pragma unroll
        for (int r = 0; r < 4; r++)
            #pragma unroll
            for (int c = 0; c < 4; c++)
                Ps[(ty * 4 + r) * APAD + tx * 4 + c] = s[r][c];
        __syncthreads();

        // O += P @ V
        #pragma unroll 8
        for (int j = 0; j < AT; j++) {
            float pa[4], vb[4];
            #pragma unroll
            for (int r = 0; r < 4; r++) pa[r] = Ps[(ty * 4 + r) * APAD + j];
            #pragma unroll
            for (int c = 0; c < 4; c++) vb[c] = Vs[j * APAD + tx * 4 + c];
            #pragma unroll
            for (int r = 0; r < 4; r++)
                #pragma unroll
                for (int c = 0; c < 4; c++)
                    o[r][c] = fmaf(pa[r], vb[c], o[r][c]);
        }
        __syncthreads();   // done reading Ks/Vs/Ps before next iter overwrites
    }

    // normalize + write
    #pragma unroll
    for (int r = 0; r < 4; r++) {
        float inv = 1.f / lsum[r];
        int row = q0 + ty * 4 + r;
        #pragma unroll
        for (int c = 0; c < 4; c++)
            AO[(size_t)row * DIM + colBase + tx * 4 + c] = o[r][c] * inv;
    }
}

// ---------------- launch ---------------------------------------------------
extern "C" void kernel_launch(void* const* d_in, const int* in_sizes, int n_in,
                              void* d_out, int out_size) {
    const float* q   = (const float*)d_in[0];
    const float* kv  = (const float*)d_in[1];
    const float* q_w = (const float*)d_in[2];
    const float* q_b = (const float*)d_in[3];
    const float* k_w = (const float*)d_in[4];
    const float* k_b = (const float*)d_in[5];
    const float* v_w = (const float*)d_in[6];
    const float* v_b = (const float*)d_in[7];
    const float* o_w = (const float*)d_in[8];
    const float* o_b = (const float*)d_in[9];
    float* out = (float*)d_out;

    float *Q, *K, *V, *AO;
    cudaGetSymbolAddress((void**)&Q,  g_Q);
    cudaGetSymbolAddress((void**)&K,  g_K);
    cudaGetSymbolAddress((void**)&V,  g_V);
    cudaGetSymbolAddress((void**)&AO, g_AO);

    dim3 gGrid(NQ / GBM, DIM / GBN);  // 32 x 8
    gemm_nt_kernel<<<gGrid, 256>>>(q,  q_w, q_b, Q, NQ,  DIM, DIM);
    gemm_nt_kernel<<<gGrid, 256>>>(kv, k_w, k_b, K, NKV, DIM, DIM);
    gemm_nt_kernel<<<gGrid, 256>>>(kv, v_w, v_b, V, NKV, DIM, DIM);

    const size_t attnSmem = (size_t)4 * AT * APAD * sizeof(float);  // ~67.6 KB
    cudaFuncSetAttribute(attn_kernel, cudaFuncAttributeMaxDynamicSharedMemorySize,
                         (int)attnSmem);
    dim3 aGrid(NQ / AT, NH);          // 64 x 16
    attn_kernel<<<aGrid, 256, attnSmem>>>(Q, K, V, AO);

    gemm_nt_kernel<<<gGrid, 256>>>(AO, o_w, o_b, out, NQ, DIM, DIM);
}

// round 4
// speedup vs baseline: 3.4546x; 3.4546x over previous
#include <cuda_runtime.h>
#include <math.h>

#define DIM 1024
#define NQ 4096
#define NKV 4096
#define NH 16
#define HD 64
#define SCALE 0.125f   // 64^-0.5

// ---------------- scratch (device globals; no allocation allowed) ----------
__device__ float g_Q[NQ * DIM];
__device__ float g_K[NKV * DIM];
__device__ float g_V[NKV * DIM];
__device__ float g_AO[NQ * DIM];

// ---------------- helpers ---------------------------------------------------
__device__ __forceinline__ float tf32r(float x) {
    unsigned u;
    asm("cvt.rna.tf32.f32 %0, %1;" : "=r"(u) : "f"(x));
    return __uint_as_float(u);
}

__device__ __forceinline__ void mma_tf32(float c[4],
                                         unsigned a0, unsigned a1, unsigned a2, unsigned a3,
                                         unsigned b0, unsigned b1) {
    asm volatile(
        "mma.sync.aligned.m16n8k8.row.col.f32.tf32.tf32.f32 "
        "{%0,%1,%2,%3},{%4,%5,%6,%7},{%8,%9},{%0,%1,%2,%3};"
        : "+f"(c[0]), "+f"(c[1]), "+f"(c[2]), "+f"(c[3])
        : "r"(a0), "r"(a1), "r"(a2), "r"(a3), "r"(b0), "r"(b1));
}

// ---------------- GEMM: C[M,N] = X[M,K] @ W[N,K]^T + b --------------------
// 128x128x32 tiles, 256 threads (8 warps as 4x2), warp tile 32x64.
#define BM 128
#define BN 128
#define BK 32
#define GP 36   // smem row pad

__global__ __launch_bounds__(256)
void gemm_tf32(const float* __restrict__ X, const float* __restrict__ W,
               const float* __restrict__ bias, float* __restrict__ C,
               int M, int N, int K) {
    __shared__ float Xs[BM][GP];
    __shared__ float Ws[BN][GP];

    const int tid = threadIdx.x;
    const int warp = tid >> 5, lane = tid & 31;
    const int g = lane >> 2, q = lane & 3;
    const int wm = warp >> 1, wn = warp & 1;          // 4 x 2 warp grid
    const int rowBase = blockIdx.x * BM;
    const int colBase = blockIdx.y * BN;

    float acc[2][8][4];
    #pragma unroll
    for (int i = 0; i < 2; i++)
        #pragma unroll
        for (int j = 0; j < 8; j++)
            #pragma unroll
            for (int v = 0; v < 4; v++) acc[i][j][v] = 0.f;

    for (int k0 = 0; k0 < K; k0 += BK) {
        // stage X and W tiles (convert to tf32)
        #pragma unroll
        for (int i = 0; i < 4; i++) {
            int idx = tid + i * 256;          // 0..1023
            int r = idx >> 3;                 // 0..127
            int c4 = (idx & 7) << 2;          // 0,4,..28
            float4 x = *reinterpret_cast<const float4*>(&X[(size_t)(rowBase + r) * K + k0 + c4]);
            Xs[r][c4 + 0] = tf32r(x.x); Xs[r][c4 + 1] = tf32r(x.y);
            Xs[r][c4 + 2] = tf32r(x.z); Xs[r][c4 + 3] = tf32r(x.w);
            float4 w = *reinterpret_cast<const float4*>(&W[(size_t)(colBase + r) * K + k0 + c4]);
            Ws[r][c4 + 0] = tf32r(w.x); Ws[r][c4 + 1] = tf32r(w.y);
            Ws[r][c4 + 2] = tf32r(w.z); Ws[r][c4 + 3] = tf32r(w.w);
        }
        __syncthreads();

        #pragma unroll
        for (int ks = 0; ks < 4; ks++) {
            const int kk = ks * 8;
            unsigned b0[8], b1[8];
            #pragma unroll
            for (int j = 0; j < 8; j++) {
                b0[j] = __float_as_uint(Ws[wn * 64 + j * 8 + g][kk + q]);
                b1[j] = __float_as_uint(Ws[wn * 64 + j * 8 + g][kk + q + 4]);
            }
            #pragma unroll
            for (int i = 0; i < 2; i++) {
                int mr = wm * 32 + i * 16 + g;
                unsigned a0 = __float_as_uint(Xs[mr][kk + q]);
                unsigned a1 = __float_as_uint(Xs[mr + 8][kk + q]);
                unsigned a2 = __float_as_uint(Xs[mr][kk + q + 4]);
                unsigned a3 = __float_as_uint(Xs[mr + 8][kk + q + 4]);
                #pragma unroll
                for (int j = 0; j < 8; j++)
                    mma_tf32(acc[i][j], a0, a1, a2, a3, b0[j], b1[j]);
            }
        }
        __syncthreads();
    }

    // epilogue
    #pragma unroll
    for (int i = 0; i < 2; i++) {
        int r0 = rowBase + wm * 32 + i * 16 + g;
        #pragma unroll
        for (int j = 0; j < 8; j++) {
            int col = colBase + wn * 64 + j * 8 + 2 * q;
            float2 bb = *reinterpret_cast<const float2*>(&bias[col]);
            float2 v0 = make_float2(acc[i][j][0] + bb.x, acc[i][j][1] + bb.y);
            float2 v1 = make_float2(acc[i][j][2] + bb.x, acc[i][j][3] + bb.y);
            *reinterpret_cast<float2*>(&C[(size_t)r0 * N + col]) = v0;
            *reinterpret_cast<float2*>(&C[(size_t)(r0 + 8) * N + col]) = v1;
        }
    }
}

// ---------------- Flash attention (tf32 mma) -------------------------------
// grid (NQ/128, NH), 256 threads (8 warps). Warp w owns q rows 16w..16w+15.
// kv tiles of 64. Q frags hoisted to registers for the whole kv loop.
#define KPAD 68
#define VPAD 72
#define PPAD 76

__global__ __launch_bounds__(256)
void attn_tf32(const float* __restrict__ Q, const float* __restrict__ K,
               const float* __restrict__ V, float* __restrict__ AO) {
    extern __shared__ float smem[];
    float* Ks = smem;                       // 64 x 68
    float* Vs = Ks + 64 * KPAD;             // 64 x 72
    float* Ps = Vs + 64 * VPAD;             // 128 x 76 (also Q staging)

    const int tid = threadIdx.x;
    const int warp = tid >> 5, lane = tid & 31;
    const int g = lane >> 2, q = lane & 3;
    const int h = blockIdx.y;
    const int q0 = blockIdx.x * 128;
    const int colBase = h * HD;

    // stage Q (128 x 64) into Ps, converted to tf32
    #pragma unroll
    for (int i = 0; i < 8; i++) {
        int idx = tid + i * 256;            // 0..2047
        int r = idx >> 4;                   // 0..127
        int c4 = (idx & 15) << 2;           // 0..60
        float4 v = *reinterpret_cast<const float4*>(&Q[(size_t)(q0 + r) * DIM + colBase + c4]);
        float* dst = &Ps[r * PPAD + c4];
        dst[0] = tf32r(v.x); dst[1] = tf32r(v.y);
        dst[2] = tf32r(v.z); dst[3] = tf32r(v.w);
    }
    __syncthreads();

    // hoist Q fragments
    unsigned qa[8][4];
    {
        float* Qw = Ps + warp * 16 * PPAD;
        #pragma unroll
        for (int s = 0; s < 8; s++) {
            qa[s][0] = __float_as_uint(Qw[g * PPAD + 8 * s + q]);
            qa[s][1] = __float_as_uint(Qw[(g + 8) * PPAD + 8 * s + q]);
            qa[s][2] = __float_as_uint(Qw[g * PPAD + 8 * s + q + 4]);
            qa[s][3] = __float_as_uint(Qw[(g + 8) * PPAD + 8 * s + q + 4]);
        }
    }

    float ofrag[8][4];
    #pragma unroll
    for (int j = 0; j < 8; j++)
        #pragma unroll
        for (int v = 0; v < 4; v++) ofrag[j][v] = 0.f;
    float m0 = -INFINITY, m1 = -INFINITY, l0 = 0.f, l1 = 0.f;

    float* Pw = Ps + warp * 16 * PPAD;      // per-warp-private P slab

    for (int kt = 0; kt < NKV / 64; kt++) {
        const int kv0 = kt * 64;
        __syncthreads();   // everyone done reading Ks/Vs from prev iter (and Ps from Q phase)
        // stage K, V tiles (64 x 64 each)
        #pragma unroll
        for (int i = 0; i < 4; i++) {
            int idx = tid + i * 256;        // 0..1023
            int r = idx >> 4;               // 0..63
            int c4 = (idx & 15) << 2;
            float4 kv4 = *reinterpret_cast<const float4*>(&K[(size_t)(kv0 + r) * DIM + colBase + c4]);
            float* kd = &Ks[r * KPAD + c4];
            kd[0] = tf32r(kv4.x); kd[1] = tf32r(kv4.y);
            kd[2] = tf32r(kv4.z); kd[3] = tf32r(kv4.w);
            float4 vv4 = *reinterpret_cast<const float4*>(&V[(size_t)(kv0 + r) * DIM + colBase + c4]);
            float* vd = &Vs[r * VPAD + c4];
            vd[0] = tf32r(vv4.x); vd[1] = tf32r(vv4.y);
            vd[2] = tf32r(vv4.z); vd[3] = tf32r(vv4.w);
        }
        __syncthreads();

        // S = Q @ K^T : sfrag[j] covers kv cols 8j..8j+7
        float sfrag[8][4];
        #pragma unroll
        for (int j = 0; j < 8; j++)
            #pragma unroll
            for (int v = 0; v < 4; v++) sfrag[j][v] = 0.f;
        #pragma unroll
        for (int s = 0; s < 8; s++) {
            unsigned b0[8], b1[8];
            #pragma unroll
            for (int j = 0; j < 8; j++) {
                b0[j] = __float_as_uint(Ks[(8 * j + g) * KPAD + 8 * s + q]);
                b1[j] = __float_as_uint(Ks[(8 * j + g) * KPAD + 8 * s + q + 4]);
            }
            #pragma unroll
            for (int j = 0; j < 8; j++)
                mma_tf32(sfrag[j], qa[s][0], qa[s][1], qa[s][2], qa[s][3], b0[j], b1[j]);
        }

        // online softmax (rows g and g+8 of this warp's 16)
        float mx0 = -INFINITY, mx1 = -INFINITY;
        #pragma unroll
        for (int j = 0; j < 8; j++) {
            mx0 = fmaxf(mx0, fmaxf(sfrag[j][0], sfrag[j][1]));
            mx1 = fmaxf(mx1, fmaxf(sfrag[j][2], sfrag[j][3]));
        }
        mx0 *= SCALE; mx1 *= SCALE;
        #pragma unroll
        for (int msk = 1; msk < 4; msk <<= 1) {
            mx0 = fmaxf(mx0, __shfl_xor_sync(0xffffffffu, mx0, msk));
            mx1 = fmaxf(mx1, __shfl_xor_sync(0xffffffffu, mx1, msk));
        }
        float mn0 = fmaxf(m0, mx0), mn1 = fmaxf(m1, mx1);
        float al0 = __expf(m0 - mn0), al1 = __expf(m1 - mn1);
        m0 = mn0; m1 = mn1;

        float rs0 = 0.f, rs1 = 0.f;
        #pragma unroll
        for (int j = 0; j < 8; j++) {
            float p0 = __expf(sfrag[j][0] * SCALE - mn0);
            float p1 = __expf(sfrag[j][1] * SCALE - mn0);
            float p2 = __expf(sfrag[j][2] * SCALE - mn1);
            float p3 = __expf(sfrag[j][3] * SCALE - mn1);
            sfrag[j][0] = p0; sfrag[j][1] = p1; sfrag[j][2] = p2; sfrag[j][3] = p3;
            rs0 += p0 + p1; rs1 += p2 + p3;
        }
        #pragma unroll
        for (int msk = 1; msk < 4; msk <<= 1) {
            rs0 += __shfl_xor_sync(0xffffffffu, rs0, msk);
            rs1 += __shfl_xor_sync(0xffffffffu, rs1, msk);
        }
        l0 = l0 * al0 + rs0;
        l1 = l1 * al1 + rs1;
        #pragma unroll
        for (int j = 0; j < 8; j++) {
            ofrag[j][0] *= al0; ofrag[j][1] *= al0;
            ofrag[j][2] *= al1; ofrag[j][3] *= al1;
        }

        // store P (tf32) to per-warp smem slab
        #pragma unroll
        for (int j = 0; j < 8; j++) {
            int col = 8 * j + 2 * q;
            *reinterpret_cast<float2*>(&Pw[g * PPAD + col]) =
                make_float2(tf32r(sfrag[j][0]), tf32r(sfrag[j][1]));
            *reinterpret_cast<float2*>(&Pw[(g + 8) * PPAD + col]) =
                make_float2(tf32r(sfrag[j][2]), tf32r(sfrag[j][3]));
        }
        __syncwarp();

        // O += P @ V
        #pragma unroll
        for (int s = 0; s < 8; s++) {
            unsigned a0 = __float_as_uint(Pw[g * PPAD + 8 * s + q]);
            unsigned a1 = __float_as_uint(Pw[(g + 8) * PPAD + 8 * s + q]);
            unsigned a2 = __float_as_uint(Pw[g * PPAD + 8 * s + q + 4]);
            unsigned a3 = __float_as_uint(Pw[(g + 8) * PPAD + 8 * s + q + 4]);
            unsigned b0[8], b1[8];
            #pragma unroll
            for (int j = 0; j < 8; j++) {
                b0[j] = __float_as_uint(Vs[(8 * s + q) * VPAD + 8 * j + g]);
                b1[j] = __float_as_uint(Vs[(8 * s + q + 4) * VPAD + 8 * j + g]);
            }
            #pragma unroll
            for (int j = 0; j < 8; j++)
                mma_tf32(ofrag[j], a0, a1, a2, a3, b0[j], b1[j]);
        }
    }

    // normalize + write
    float inv0 = 1.f / l0, inv1 = 1.f / l1;
    int r0 = q0 + warp * 16 + g;
    #pragma unroll
    for (int j = 0; j < 8; j++) {
        int col = colBase + 8 * j + 2 * q;
        *reinterpret_cast<float2*>(&AO[(size_t)r0 * DIM + col]) =
            make_float2(ofrag[j][0] * inv0, ofrag[j][1] * inv0);
        *reinterpret_cast<float2*>(&AO[(size_t)(r0 + 8) * DIM + col]) =
            make_float2(ofrag[j][2] * inv1, ofrag[j][3] * inv1);
    }
}

// ---------------- launch ---------------------------------------------------
extern "C" void kernel_launch(void* const* d_in, const int* in_sizes, int n_in,
                              void* d_out, int out_size) {
    const float* q   = (const float*)d_in[0];
    const float* kv  = (const float*)d_in[1];
    const float* q_w = (const float*)d_in[2];
    const float* q_b = (const float*)d_in[3];
    const float* k_w = (const float*)d_in[4];
    const float* k_b = (const float*)d_in[5];
    const float* v_w = (const float*)d_in[6];
    const float* v_b = (const float*)d_in[7];
    const float* o_w = (const float*)d_in[8];
    const float* o_b = (const float*)d_in[9];
    float* out = (float*)d_out;

    float *Q, *K, *V, *AO;
    cudaGetSymbolAddress((void**)&Q,  g_Q);
    cudaGetSymbolAddress((void**)&K,  g_K);
    cudaGetSymbolAddress((void**)&V,  g_V);
    cudaGetSymbolAddress((void**)&AO, g_AO);

    dim3 gGrid(NQ / BM, DIM / BN);  // 32 x 8
    gemm_tf32<<<gGrid, 256>>>(q,  q_w, q_b, Q, NQ,  DIM, DIM);
    gemm_tf32<<<gGrid, 256>>>(kv, k_w, k_b, K, NKV, DIM, DIM);
    gemm_tf32<<<gGrid, 256>>>(kv, v_w, v_b, V, NKV, DIM, DIM);

    const size_t attnSmem = (size_t)(64 * KPAD + 64 * VPAD + 128 * PPAD) * sizeof(float);
    cudaFuncSetAttribute(attn_tf32, cudaFuncAttributeMaxDynamicSharedMemorySize,
                         (int)attnSmem);
    dim3 aGrid(NQ / 128, NH);       // 32 x 16
    attn_tf32<<<aGrid, 256, attnSmem>>>(Q, K, V, AO);

    gemm_tf32<<<gGrid, 256>>>(AO, o_w, o_b, out, NQ, DIM, DIM);
}